// round 4
// baseline (speedup 1.0000x reference)
#include <cuda_runtime.h>
#include <math.h>

#define BN 512
#define CC 3
#define NP 49
#define NT 76
#define DD 768
#define EPSI 0.1f
#define THRESH 0.01f
#define MAX_ITER 100

#define NBLK 128          // sinkhorn persistent blocks (must be <= SM count)
#define STPB 512          // sinkhorn threads per block
#define SKP (49*77)       // padded K tile stride (3773 floats)
#define KSPLIT 6

// ------------------------- device scratch (no allocs allowed) ----------------
__device__ float g_K[(size_t)CC*BN*NP*NT];        // exp kernel per (c,b)
__device__ float g_Gp[(size_t)KSPLIT*BN*BN];      // split-K partials of logits GEMM
__device__ float g_L[(size_t)BN*BN];              // logits_per_image
__device__ float g_lse_row[BN];
__device__ float g_lse_col[BN];
__device__ float g_err_part[3*NBLK];
__device__ float g_ot_part[NBLK];
__device__ unsigned g_count;
__device__ unsigned g_gen;
__device__ unsigned g_mask;
__device__ int g_iter[3];

// ------------------------------ init ----------------------------------------
__global__ void init_state_kernel() {
    g_count = 0u;
    g_gen = 0u;
    g_mask = 7u;
    g_iter[0] = 0; g_iter[1] = 0; g_iter[2] = 0;
}

// --------------------- sim + K kernel: one block per (b,c) -------------------
// Computes K[c,b,n,m] = exp(-(1 - sim)/eps), sim = normalized dot of
// li[b,c,n,:] with lt[b,c,m,:].
__global__ void __launch_bounds__(256) simK_kernel(const float* __restrict__ li,
                                                   const float* __restrict__ lt) {
    __shared__ __align__(16) float As[56*68];   // n-major, rows padded to 56, k stride 68
    __shared__ float Bs[64*97];                 // k-major, m padded to 96, stride 97
    __shared__ float inv_na[56];
    __shared__ float inv_nb[96];

    const int blk = blockIdx.x;        // b*3 + c
    const int b = blk / 3;
    const int c = blk - b*3;
    const float4* A4 = reinterpret_cast<const float4*>(li + ((size_t)(b*CC + c))*NP*DD);
    const float4* B4 = reinterpret_cast<const float4*>(lt + ((size_t)(b*CC + c))*NT*DD);

    const int tid = threadIdx.x;
    const int lane = tid & 31;
    const int w = tid >> 5;            // 8 warps

    // ---- phase 0: inverse norms (re-read hits L2 during GEMM phase) ----
    for (int row = w; row < NP; row += 8) {
        float ss = 0.f;
        for (int q = lane; q < 192; q += 32) {
            float4 v = A4[row*192 + q];
            ss += v.x*v.x + v.y*v.y + v.z*v.z + v.w*v.w;
        }
        #pragma unroll
        for (int o = 16; o; o >>= 1) ss += __shfl_xor_sync(0xffffffffu, ss, o);
        if (lane == 0) inv_na[row] = 1.0f / fmaxf(sqrtf(ss), 1e-12f);
    }
    for (int row = w; row < NT; row += 8) {
        float ss = 0.f;
        for (int q = lane; q < 192; q += 32) {
            float4 v = B4[row*192 + q];
            ss += v.x*v.x + v.y*v.y + v.z*v.z + v.w*v.w;
        }
        #pragma unroll
        for (int o = 16; o; o >>= 1) ss += __shfl_xor_sync(0xffffffffu, ss, o);
        if (lane == 0) inv_nb[row] = 1.0f / fmaxf(sqrtf(ss), 1e-12f);
    }

    const int tx = tid & 31;           // m lane
    const int ty = tid >> 5;           // n group (8)
    float acc[7][3];
    #pragma unroll
    for (int j = 0; j < 7; j++) { acc[j][0] = 0.f; acc[j][1] = 0.f; acc[j][2] = 0.f; }

    // ---- main loop: 12 chunks of k=64 ----
    for (int kc = 0; kc < 12; kc++) {
        const int k0q = kc * 16;       // float4 offset within row
        __syncthreads();
        // fill A tile (n-major)
        for (int e = tid; e < 56*16; e += 256) {
            int row = e >> 4, q = e & 15;
            float4 v = (row < NP) ? A4[row*192 + k0q + q] : make_float4(0.f,0.f,0.f,0.f);
            *reinterpret_cast<float4*>(&As[row*68 + 4*q]) = v;
        }
        // fill B tile transposed (k-major)
        for (int e = tid; e < 96*16; e += 256) {
            int m = e >> 4, q = e & 15;
            float4 v = (m < NT) ? B4[m*192 + k0q + q] : make_float4(0.f,0.f,0.f,0.f);
            int kk = 4*q;
            Bs[(kk+0)*97 + m] = v.x;
            Bs[(kk+1)*97 + m] = v.y;
            Bs[(kk+2)*97 + m] = v.z;
            Bs[(kk+3)*97 + m] = v.w;
        }
        __syncthreads();

        #pragma unroll 2
        for (int k = 0; k < 64; k += 4) {
            float4 a4[7];
            #pragma unroll
            for (int j = 0; j < 7; j++)
                a4[j] = *reinterpret_cast<const float4*>(&As[(ty + 8*j)*68 + k]);
            #pragma unroll
            for (int kk = 0; kk < 4; kk++) {
                float b0 = Bs[(k+kk)*97 + tx];
                float b1 = Bs[(k+kk)*97 + tx + 32];
                float b2 = Bs[(k+kk)*97 + tx + 64];
                #pragma unroll
                for (int j = 0; j < 7; j++) {
                    float av = (kk == 0) ? a4[j].x : (kk == 1) ? a4[j].y
                             : (kk == 2) ? a4[j].z : a4[j].w;
                    acc[j][0] = fmaf(av, b0, acc[j][0]);
                    acc[j][1] = fmaf(av, b1, acc[j][1]);
                    acc[j][2] = fmaf(av, b2, acc[j][2]);
                }
            }
        }
    }

    // ---- epilogue: sim -> K ----
    const size_t base = (size_t)(c*BN + b) * (NP*NT);
    #pragma unroll
    for (int j = 0; j < 7; j++) {
        int n = ty + 8*j;
        if (n < NP) {
            float ina = inv_na[n];
            #pragma unroll
            for (int jm = 0; jm < 3; jm++) {
                int m = tx + 32*jm;
                if (m < NT) {
                    float sim = acc[j][jm] * ina * inv_nb[m];
                    g_K[base + (size_t)n*NT + m] = expf(-(1.0f - sim) / EPSI);
                }
            }
        }
    }
}

// ------------------------- persistent Sinkhorn kernel ------------------------
// 128 blocks, each owns 4 batches x 3 channels fully in smem. Per-channel
// global convergence via one sense-reversing barrier per iteration.
extern __shared__ float sh[];
__global__ void __launch_bounds__(STPB) sinkhorn_kernel() {
    float* sK  = sh;                       // 12*SKP
    float* r_s = sK + 12*SKP;              // 12*52
    float* c_s = r_s + 12*52;              // 12*80
    float* red = c_s + 12*80;              // 3*STPB
    __shared__ unsigned s_mask;

    const int tid = threadIdx.x;
    const int blk = blockIdx.x;

    // load K tiles (padded stride 77)
    for (int p = 0; p < 12; p++) {
        int ch = p >> 2;
        int b  = blk*4 + (p & 3);
        const float* src = g_K + (size_t)(ch*BN + b) * (NP*NT);
        for (int e = tid; e < NP*NT; e += STPB) {
            int n = e / NT, m = e - n*NT;
            sK[p*SKP + n*77 + m] = src[e];
        }
    }
    for (int e = tid; e < 12*52; e += STPB) r_s[e] = 1.0f;
    for (int e = tid; e < 12*80; e += STPB) c_s[e] = 1.0f;
    if (tid == 0) s_mask = 7u;
    __syncthreads();

    unsigned gen = 0;
    unsigned mask = 7u;
    const float U = 1.0f / (float)NP;
    const float V = 1.0f / (float)NT;

    while (mask) {
        float e0 = 0.f, e1 = 0.f, e2 = 0.f;
        // r update: r = u / (K c)   (also accumulates |r_new - r_old|)
        for (int idx = tid; idx < 12*NP; idx += STPB) {
            int p = idx / NP, n = idx - p*NP;
            int ch = p >> 2;
            if (mask & (1u << ch)) {
                const float* Kr = &sK[p*SKP + n*77];
                const float* cp = &c_s[p*80];
                float s = 0.f;
                #pragma unroll 4
                for (int m = 0; m < NT; m++) s = fmaf(Kr[m], cp[m], s);
                float rn = U / s;
                float d = fabsf(rn - r_s[p*52 + n]);
                if (ch == 0) e0 += d; else if (ch == 1) e1 += d; else e2 += d;
                r_s[p*52 + n] = rn;
            }
        }
        __syncthreads();
        // c update: c = v / (K^T r)
        for (int idx = tid; idx < 12*NT; idx += STPB) {
            int p = idx / NT, m = idx - p*NT;
            int ch = p >> 2;
            if (mask & (1u << ch)) {
                const float* Kc = &sK[p*SKP + m];
                const float* rp = &r_s[p*52];
                float s = 0.f;
                #pragma unroll 7
                for (int n = 0; n < NP; n++) s = fmaf(Kc[n*77], rp[n], s);
                c_s[p*80 + m] = V / s;
            }
        }
        // deterministic block reduction of the 3 error partials
        red[tid] = e0; red[STPB + tid] = e1; red[2*STPB + tid] = e2;
        __syncthreads();
        for (int st = STPB/2; st > 0; st >>= 1) {
            if (tid < st) {
                red[tid]          += red[tid + st];
                red[STPB + tid]   += red[STPB + tid + st];
                red[2*STPB + tid] += red[2*STPB + tid + st];
            }
            __syncthreads();
        }
        if (tid == 0) {
            g_err_part[0*NBLK + blk] = red[0];
            g_err_part[1*NBLK + blk] = red[STPB];
            g_err_part[2*NBLK + blk] = red[2*STPB];
            __threadfence();
            unsigned my = atomicAdd(&g_count, 1u);
            gen++;
            if (my == NBLK - 1) {
                // master: reduce errors, advance per-channel state
                __threadfence();
                unsigned om = g_mask, nm = om;
                for (int ch = 0; ch < 3; ch++) {
                    if (om & (1u << ch)) {
                        float s = 0.f;
                        for (int i2 = 0; i2 < NBLK; i2++) s += g_err_part[ch*NBLK + i2];
                        float err = s * (1.0f / (float)(BN*NP));
                        int it = g_iter[ch] + 1;
                        g_iter[ch] = it;
                        if (!(it < MAX_ITER && err >= THRESH)) nm &= ~(1u << ch);
                    }
                }
                g_mask = nm;
                g_count = 0u;
                __threadfence();
                atomicAdd(&g_gen, 1u);
            } else {
                unsigned cur;
                do {
                    asm volatile("ld.acquire.gpu.u32 %0, [%1];" : "=r"(cur) : "l"(&g_gen));
                    if (cur < gen) __nanosleep(64);
                } while (cur < gen);
            }
            __threadfence();
            s_mask = g_mask;
        }
        __syncthreads();
        mask = s_mask;
    }

    // OT contribution: sum r*c*K*sim with sim = 1 + eps*log(K)
    float ot = 0.f;
    for (int p = 0; p < 12; p++) {
        const float* Kp = &sK[p*SKP];
        const float* rp = &r_s[p*52];
        const float* cp = &c_s[p*80];
        for (int e = tid; e < NP*NT; e += STPB) {
            int n = e / NT, m = e - n*NT;
            float Kv = Kp[n*77 + m];
            float simv = fmaf(EPSI, logf(Kv), 1.0f);
            ot = fmaf(rp[n]*cp[m], Kv*simv, ot);
        }
    }
    red[tid] = ot;
    __syncthreads();
    for (int st = STPB/2; st > 0; st >>= 1) {
        if (tid < st) red[tid] += red[tid + st];
        __syncthreads();
    }
    if (tid == 0) g_ot_part[blk] = red[0];
}

// -------------------- logits GEMM: 512x512x2304, split-K ---------------------
__global__ void __launch_bounds__(256) gemm_logits_kernel(const float* __restrict__ img,
                                                          const float* __restrict__ txt) {
    __shared__ float As[32*68];   // k-major
    __shared__ float Bs[32*68];   // k-major
    const int bx = blockIdx.x, by = blockIdx.y, bz = blockIdx.z;
    const int tid = threadIdx.x;
    const int tx = tid & 15, ty = tid >> 4;
    const int rowA = by * 64, rowB = bx * 64;
    const float4* A4 = reinterpret_cast<const float4*>(img);
    const float4* B4 = reinterpret_cast<const float4*>(txt);

    float acc[4][4];
    #pragma unroll
    for (int i = 0; i < 4; i++)
        #pragma unroll
        for (int j = 0; j < 4; j++) acc[i][j] = 0.f;

    for (int kc = 0; kc < 12; kc++) {
        const int kq = bz*96 + kc*8;   // float4 offset, 2304/4 = 576 per row
        __syncthreads();
        for (int e = tid; e < 512; e += 256) {
            int r = e >> 3, q = e & 7;
            float4 va = A4[(size_t)(rowA + r)*576 + kq + q];
            float4 vb = B4[(size_t)(rowB + r)*576 + kq + q];
            int kk = 4*q;
            As[(kk+0)*68 + r] = va.x; As[(kk+1)*68 + r] = va.y;
            As[(kk+2)*68 + r] = va.z; As[(kk+3)*68 + r] = va.w;
            Bs[(kk+0)*68 + r] = vb.x; Bs[(kk+1)*68 + r] = vb.y;
            Bs[(kk+2)*68 + r] = vb.z; Bs[(kk+3)*68 + r] = vb.w;
        }
        __syncthreads();
        #pragma unroll 8
        for (int k = 0; k < 32; k++) {
            float a0 = As[k*68 + ty],      a1 = As[k*68 + ty + 16];
            float a2 = As[k*68 + ty + 32], a3 = As[k*68 + ty + 48];
            float b0 = Bs[k*68 + tx],      b1 = Bs[k*68 + tx + 16];
            float b2 = Bs[k*68 + tx + 32], b3 = Bs[k*68 + tx + 48];
            acc[0][0]=fmaf(a0,b0,acc[0][0]); acc[0][1]=fmaf(a0,b1,acc[0][1]);
            acc[0][2]=fmaf(a0,b2,acc[0][2]); acc[0][3]=fmaf(a0,b3,acc[0][3]);
            acc[1][0]=fmaf(a1,b0,acc[1][0]); acc[1][1]=fmaf(a1,b1,acc[1][1]);
            acc[1][2]=fmaf(a1,b2,acc[1][2]); acc[1][3]=fmaf(a1,b3,acc[1][3]);
            acc[2][0]=fmaf(a2,b0,acc[2][0]); acc[2][1]=fmaf(a2,b1,acc[2][1]);
            acc[2][2]=fmaf(a2,b2,acc[2][2]); acc[2][3]=fmaf(a2,b3,acc[2][3]);
            acc[3][0]=fmaf(a3,b0,acc[3][0]); acc[3][1]=fmaf(a3,b1,acc[3][1]);
            acc[3][2]=fmaf(a3,b2,acc[3][2]); acc[3][3]=fmaf(a3,b3,acc[3][3]);
        }
    }
    float* out = g_Gp + (size_t)bz * BN * BN;
    #pragma unroll
    for (int i = 0; i < 4; i++)
        #pragma unroll
        for (int j = 0; j < 4; j++)
            out[(size_t)(rowA + ty + 16*i)*BN + rowB + tx + 16*j] = acc[i][j];
}

__global__ void reduce_scale_kernel(const float* __restrict__ scale_p) {
    const size_t i = (size_t)blockIdx.x * 512 + threadIdx.x;
    const float s = scale_p[0] / (float)CC;
    float v = 0.f;
    #pragma unroll
    for (int j = 0; j < KSPLIT; j++) v += g_Gp[(size_t)j*BN*BN + i];
    g_L[i] = s * v;
}

// --------------------------- LSE + finalize ----------------------------------
__global__ void row_lse_kernel() {
    __shared__ float red[256];
    const int b = blockIdx.x, t = threadIdx.x;
    const float* row = g_L + (size_t)b * BN;
    float x0 = row[t], x1 = row[t + 256];
    red[t] = fmaxf(x0, x1);
    __syncthreads();
    for (int st = 128; st > 0; st >>= 1) {
        if (t < st) red[t] = fmaxf(red[t], red[t + st]);
        __syncthreads();
    }
    float M = red[0];
    __syncthreads();
    red[t] = expf(x0 - M) + expf(x1 - M);
    __syncthreads();
    for (int st = 128; st > 0; st >>= 1) {
        if (t < st) red[t] += red[t + st];
        __syncthreads();
    }
    if (t == 0) g_lse_row[b] = M + logf(red[0]);
}

__global__ void col_lse_kernel() {
    __shared__ float red[256];
    const int b = blockIdx.x, t = threadIdx.x;
    float x0 = g_L[(size_t)t * BN + b], x1 = g_L[(size_t)(t + 256) * BN + b];
    red[t] = fmaxf(x0, x1);
    __syncthreads();
    for (int st = 128; st > 0; st >>= 1) {
        if (t < st) red[t] = fmaxf(red[t], red[t + st]);
        __syncthreads();
    }
    float M = red[0];
    __syncthreads();
    red[t] = expf(x0 - M) + expf(x1 - M);
    __syncthreads();
    for (int st = 128; st > 0; st >>= 1) {
        if (t < st) red[t] += red[t + st];
        __syncthreads();
    }
    if (t == 0) g_lse_col[b] = M + logf(red[0]);
}

__global__ void finalize_kernel(float* __restrict__ out) {
    __shared__ float r1[512], r2[512], r3[512];
    const int t = threadIdx.x;
    float diag = g_L[(size_t)t * BN + t];
    r1[t] = g_lse_row[t] - diag;
    r2[t] = g_lse_col[t] - diag;
    r3[t] = (t < NBLK) ? g_ot_part[t] : 0.f;
    __syncthreads();
    for (int st = 256; st > 0; st >>= 1) {
        if (t < st) { r1[t] += r1[t+st]; r2[t] += r2[t+st]; r3[t] += r3[t+st]; }
        __syncthreads();
    }
    if (t == 0)
        out[0] = (r1[0] + r2[0]) * (0.5f / (float)BN) + r3[0];
}

// ------------------------------- launch --------------------------------------
extern "C" void kernel_launch(void* const* d_in, const int* in_sizes, int n_in,
                              void* d_out, int out_size) {
    (void)in_sizes; (void)n_in; (void)out_size;
    const float* img   = (const float*)d_in[0];
    const float* txt   = (const float*)d_in[1];
    const float* scale = (const float*)d_in[2];
    const float* li    = (const float*)d_in[3];
    const float* lt    = (const float*)d_in[4];
    float* out = (float*)d_out;

    const size_t sk_smem = (size_t)(12*SKP + 12*52 + 12*80 + 3*STPB) * sizeof(float);
    cudaFuncSetAttribute(sinkhorn_kernel,
                         cudaFuncAttributeMaxDynamicSharedMemorySize, (int)sk_smem);

    init_state_kernel<<<1, 1>>>();
    simK_kernel<<<BN*CC, 256>>>(li, lt);
    sinkhorn_kernel<<<NBLK, STPB, sk_smem>>>();
    dim3 gg(8, 8, KSPLIT);
    gemm_logits_kernel<<<gg, 256>>>(img, txt);
    reduce_scale_kernel<<<512, 512>>>(scale);
    row_lse_kernel<<<BN, 256>>>();
    col_lse_kernel<<<BN, 256>>>();
    finalize_kernel<<<1, 512>>>(out);
}

// round 6
// speedup vs baseline: 2.0782x; 2.0782x over previous
#include <cuda_runtime.h>
#include <cuda_bf16.h>
#include <cstdint>
#include <math.h>

#define BN 512
#define CC 3
#define NP 49
#define NT 76
#define DD 768
#define EPSI 0.1f
#define THRESH 0.01f
#define MAX_ITER 100

#define NBLK 128          // sinkhorn persistent blocks (must be <= SM count)
#define STPB 512          // sinkhorn threads per block
#define SKP (49*77)       // padded K tile stride (3773 floats)
#define KSPLIT 6

// ------------------------- device scratch (no allocs allowed) ----------------
__device__ float g_K[(size_t)CC*BN*NP*NT];        // exp kernel per (c,b)
__device__ float g_Gp[(size_t)KSPLIT*BN*BN];      // split-K partials of logits GEMM
__device__ float g_L[(size_t)BN*BN];              // logits_per_image
__device__ float g_lse_row[BN];
__device__ float g_lse_col[BN];
__device__ float g_err_part[3*NBLK];
__device__ float g_ot_part[NBLK];
__device__ unsigned g_count;
__device__ unsigned g_gen;
__device__ unsigned g_mask;
__device__ int g_iter[3];

// ------------------------------ init ----------------------------------------
__global__ void init_state_kernel() {
    g_count = 0u;
    g_gen = 0u;
    g_mask = 7u;
    g_iter[0] = 0; g_iter[1] = 0; g_iter[2] = 0;
}

// --------------------- sim + K kernel (bf16 tensor cores) --------------------
// One block per (b,c). M=64 (49 real) x N=80 (76 real) x K=768.
// 8 warps: 4 (m) x 2 (n); each warp: 1 m16 tile x 5 n8 frags, mma.m16n8k16 bf16.
// fp32 -> bf16 conversion fused into smem fill; row norms accumulated in the
// same pass (deterministic fixed-owner accumulation).

__device__ __forceinline__ uint32_t pack_bf16(float x, float y) {
    __nv_bfloat162 h = __floats2bfloat162_rn(x, y);  // .x = x in low 16 bits
    return *reinterpret_cast<uint32_t*>(&h);
}

__global__ void __launch_bounds__(256) simK_kernel(const float* __restrict__ li,
                                                   const float* __restrict__ lt) {
    // padded bf16 tiles as 32-bit words; row stride 20 words (16 data + 4 pad)
    __shared__ uint32_t As32[64*20];
    __shared__ uint32_t Bs32[80*20];
    __shared__ float normA[64];
    __shared__ float normB[80];

    const int blk = blockIdx.x;        // b*3 + c
    const int b = blk / 3;
    const int c = blk - b*3;
    const float4* A4 = reinterpret_cast<const float4*>(li + ((size_t)(b*CC + c))*NP*DD);
    const float4* B4 = reinterpret_cast<const float4*>(lt + ((size_t)(b*CC + c))*NT*DD);

    const int t = threadIdx.x;
    const int lane = t & 31;
    const int w = t >> 5;
    const int gid = lane >> 2;          // 0..7
    const int tig = lane & 3;           // 0..3

    // fill roles: threads 0..97 -> A (row = t/2, half = t&1)
    //             threads 104..255 -> B (tb = t-104, row = tb/2, half = tb&1)
    const bool isA = (t < 98);
    const bool isB = (t >= 104);
    const int arow = t >> 1;
    const int tb = t - 104;
    const int brow = tb >> 1;
    const int q0A = (t & 1) * 4;
    const int q0B = (tb & 1) * 4;

    // zero norms + pad rows (pad rows written once; never overwritten)
    if (t < 64) normA[t] = 0.f;
    if (t >= 64 && t < 144) normB[t - 64] = 0.f;
    for (int e = t; e < (15 + 4) * 16; e += 256) {
        int rr = e >> 4, ww = e & 15;
        if (rr < 15) As32[(49 + rr)*20 + ww] = 0u;
        else         Bs32[(76 + (rr - 15))*20 + ww] = 0u;
    }

    // warp tiling
    const int wm = w >> 1;              // 0..3
    const int wn = w & 1;               // 0..1
    const int r0 = wm*16 + gid;
    const int r1 = r0 + 8;

    float acc[5][4];
    #pragma unroll
    for (int f = 0; f < 5; f++) {
        acc[f][0] = 0.f; acc[f][1] = 0.f; acc[f][2] = 0.f; acc[f][3] = 0.f;
    }

    for (int kc = 0; kc < 24; kc++) {
        __syncthreads();   // previous compute done reading smem (and pads ready)
        // ---- fill: load fp32, convert to bf16, accumulate sum-of-squares ----
        float ss = 0.f;
        if (isA) {
            const float4* src = A4 + arow*192 + kc*8 + q0A;
            #pragma unroll
            for (int i = 0; i < 4; i++) {
                float4 v = src[i];
                ss += v.x*v.x + v.y*v.y + v.z*v.z + v.w*v.w;
                int wbase = arow*20 + (q0A + i)*2;
                As32[wbase]     = pack_bf16(v.x, v.y);
                As32[wbase + 1] = pack_bf16(v.z, v.w);
            }
        } else if (isB) {
            const float4* src = B4 + brow*192 + kc*8 + q0B;
            #pragma unroll
            for (int i = 0; i < 4; i++) {
                float4 v = src[i];
                ss += v.x*v.x + v.y*v.y + v.z*v.z + v.w*v.w;
                int wbase = brow*20 + (q0B + i)*2;
                Bs32[wbase]     = pack_bf16(v.x, v.y);
                Bs32[wbase + 1] = pack_bf16(v.z, v.w);
            }
        }
        ss += __shfl_xor_sync(0xffffffffu, ss, 1);   // pair halves of each row
        if (isA && (t & 1) == 0) normA[arow] += ss;  // single fixed owner -> deterministic
        if (isB && (tb & 1) == 0) normB[brow] += ss;
        __syncthreads();

        // ---- compute: 2 k16 steps per chunk ----
        #pragma unroll
        for (int ks = 0; ks < 2; ks++) {
            const int kw = ks * 8;
            uint32_t a0 = As32[r0*20 + kw + tig];
            uint32_t a1 = As32[r1*20 + kw + tig];
            uint32_t a2 = As32[r0*20 + kw + 4 + tig];
            uint32_t a3 = As32[r1*20 + kw + 4 + tig];
            #pragma unroll
            for (int f = 0; f < 5; f++) {
                int n = wn*40 + f*8 + gid;
                uint32_t b0 = Bs32[n*20 + kw + tig];
                uint32_t b1 = Bs32[n*20 + kw + 4 + tig];
                asm volatile(
                    "mma.sync.aligned.m16n8k16.row.col.f32.bf16.bf16.f32 "
                    "{%0,%1,%2,%3}, {%4,%5,%6,%7}, {%8,%9}, {%0,%1,%2,%3};"
                    : "+f"(acc[f][0]), "+f"(acc[f][1]), "+f"(acc[f][2]), "+f"(acc[f][3])
                    : "r"(a0), "r"(a1), "r"(a2), "r"(a3), "r"(b0), "r"(b1));
            }
        }
    }

    // ---- norms -> inverse norms (in place) ----
    __syncthreads();
    if (t < 64)                normA[t]      = 1.0f / fmaxf(sqrtf(normA[t]), 1e-12f);
    if (t >= 64 && t < 144)    normB[t - 64] = 1.0f / fmaxf(sqrtf(normB[t - 64]), 1e-12f);
    __syncthreads();

    // ---- epilogue: sim -> K ----
    const size_t base = (size_t)(c*BN + b) * (NP*NT);
    const float ia0 = (r0 < NP) ? normA[r0] : 0.f;
    const float ia1 = (r1 < NP) ? normA[r1] : 0.f;
    #pragma unroll
    for (int f = 0; f < 5; f++) {
        int col = wn*40 + f*8 + tig*2;
        float ib0 = normB[col];
        float ib1 = normB[col + 1];
        if (col < NT) {
            if (r0 < NP) {
                float s0 = acc[f][0] * ia0 * ib0;
                float s1 = acc[f][1] * ia0 * ib1;
                g_K[base + (size_t)r0*NT + col] = expf(fmaf(10.0f, s0, -10.0f));
                if (col + 1 < NT)
                    g_K[base + (size_t)r0*NT + col + 1] = expf(fmaf(10.0f, s1, -10.0f));
            }
            if (r1 < NP) {
                float s2 = acc[f][2] * ia1 * ib0;
                float s3 = acc[f][3] * ia1 * ib1;
                g_K[base + (size_t)r1*NT + col] = expf(fmaf(10.0f, s2, -10.0f));
                if (col + 1 < NT)
                    g_K[base + (size_t)r1*NT + col + 1] = expf(fmaf(10.0f, s3, -10.0f));
            }
        }
    }
}

// ------------------------- persistent Sinkhorn kernel ------------------------
// 128 blocks, each owns 4 batches x 3 channels fully in smem. Per-channel
// global convergence via one sense-reversing barrier per iteration.
extern __shared__ float sh[];
__global__ void __launch_bounds__(STPB) sinkhorn_kernel() {
    float* sK  = sh;                       // 12*SKP
    float* r_s = sK + 12*SKP;              // 12*52
    float* c_s = r_s + 12*52;              // 12*80
    float* red = c_s + 12*80;              // 3*STPB
    __shared__ unsigned s_mask;

    const int tid = threadIdx.x;
    const int blk = blockIdx.x;

    // load K tiles (padded stride 77)
    for (int p = 0; p < 12; p++) {
        int ch = p >> 2;
        int b  = blk*4 + (p & 3);
        const float* src = g_K + (size_t)(ch*BN + b) * (NP*NT);
        for (int e = tid; e < NP*NT; e += STPB) {
            int n = e / NT, m = e - n*NT;
            sK[p*SKP + n*77 + m] = src[e];
        }
    }
    for (int e = tid; e < 12*52; e += STPB) r_s[e] = 1.0f;
    for (int e = tid; e < 12*80; e += STPB) c_s[e] = 1.0f;
    if (tid == 0) s_mask = 7u;
    __syncthreads();

    unsigned gen = 0;
    unsigned mask = 7u;
    const float U = 1.0f / (float)NP;
    const float V = 1.0f / (float)NT;

    while (mask) {
        float e0 = 0.f, e1 = 0.f, e2 = 0.f;
        // r update: r = u / (K c)   (also accumulates |r_new - r_old|)
        for (int idx = tid; idx < 12*NP; idx += STPB) {
            int p = idx / NP, n = idx - p*NP;
            int ch = p >> 2;
            if (mask & (1u << ch)) {
                const float* Kr = &sK[p*SKP + n*77];
                const float* cp = &c_s[p*80];
                float s = 0.f;
                #pragma unroll 4
                for (int m = 0; m < NT; m++) s = fmaf(Kr[m], cp[m], s);
                float rn = U / s;
                float d = fabsf(rn - r_s[p*52 + n]);
                if (ch == 0) e0 += d; else if (ch == 1) e1 += d; else e2 += d;
                r_s[p*52 + n] = rn;
            }
        }
        __syncthreads();
        // c update: c = v / (K^T r)
        for (int idx = tid; idx < 12*NT; idx += STPB) {
            int p = idx / NT, m = idx - p*NT;
            int ch = p >> 2;
            if (mask & (1u << ch)) {
                const float* Kc = &sK[p*SKP + m];
                const float* rp = &r_s[p*52];
                float s = 0.f;
                #pragma unroll 7
                for (int n = 0; n < NP; n++) s = fmaf(Kc[n*77], rp[n], s);
                c_s[p*80 + m] = V / s;
            }
        }
        // deterministic block reduction of the 3 error partials
        red[tid] = e0; red[STPB + tid] = e1; red[2*STPB + tid] = e2;
        __syncthreads();
        for (int st = STPB/2; st > 0; st >>= 1) {
            if (tid < st) {
                red[tid]          += red[tid + st];
                red[STPB + tid]   += red[STPB + tid + st];
                red[2*STPB + tid] += red[2*STPB + tid + st];
            }
            __syncthreads();
        }
        if (tid == 0) {
            g_err_part[0*NBLK + blk] = red[0];
            g_err_part[1*NBLK + blk] = red[STPB];
            g_err_part[2*NBLK + blk] = red[2*STPB];
            __threadfence();
            unsigned my = atomicAdd(&g_count, 1u);
            gen++;
            if (my == NBLK - 1) {
                // master: reduce errors, advance per-channel state
                __threadfence();
                unsigned om = g_mask, nm = om;
                for (int ch = 0; ch < 3; ch++) {
                    if (om & (1u << ch)) {
                        float s = 0.f;
                        for (int i2 = 0; i2 < NBLK; i2++) s += g_err_part[ch*NBLK + i2];
                        float err = s * (1.0f / (float)(BN*NP));
                        int it = g_iter[ch] + 1;
                        g_iter[ch] = it;
                        if (!(it < MAX_ITER && err >= THRESH)) nm &= ~(1u << ch);
                    }
                }
                g_mask = nm;
                g_count = 0u;
                __threadfence();
                atomicAdd(&g_gen, 1u);
            } else {
                unsigned cur;
                do {
                    asm volatile("ld.acquire.gpu.u32 %0, [%1];" : "=r"(cur) : "l"(&g_gen));
                    if (cur < gen) __nanosleep(64);
                } while (cur < gen);
            }
            __threadfence();
            s_mask = g_mask;
        }
        __syncthreads();
        mask = s_mask;
    }

    // OT contribution: sum r*c*K*sim with sim = 1 + eps*log(K)
    float ot = 0.f;
    for (int p = 0; p < 12; p++) {
        const float* Kp = &sK[p*SKP];
        const float* rp = &r_s[p*52];
        const float* cp = &c_s[p*80];
        for (int e = tid; e < NP*NT; e += STPB) {
            int n = e / NT, m = e - n*NT;
            float Kv = Kp[n*77 + m];
            float simv = fmaf(EPSI, logf(Kv), 1.0f);
            ot = fmaf(rp[n]*cp[m], Kv*simv, ot);
        }
    }
    red[tid] = ot;
    __syncthreads();
    for (int st = STPB/2; st > 0; st >>= 1) {
        if (tid < st) red[tid] += red[tid + st];
        __syncthreads();
    }
    if (tid == 0) g_ot_part[blk] = red[0];
}

// -------------------- logits GEMM: 512x512x2304, split-K ---------------------
__global__ void __launch_bounds__(256) gemm_logits_kernel(const float* __restrict__ img,
                                                          const float* __restrict__ txt) {
    __shared__ float As[32*68];   // k-major
    __shared__ float Bs[32*68];   // k-major
    const int bx = blockIdx.x, by = blockIdx.y, bz = blockIdx.z;
    const int tid = threadIdx.x;
    const int tx = tid & 15, ty = tid >> 4;
    const int rowA = by * 64, rowB = bx * 64;
    const float4* A4 = reinterpret_cast<const float4*>(img);
    const float4* B4 = reinterpret_cast<const float4*>(txt);

    float acc[4][4];
    #pragma unroll
    for (int i = 0; i < 4; i++)
        #pragma unroll
        for (int j = 0; j < 4; j++) acc[i][j] = 0.f;

    for (int kc = 0; kc < 12; kc++) {
        const int kq = bz*96 + kc*8;   // float4 offset, 2304/4 = 576 per row
        __syncthreads();
        for (int e = tid; e < 512; e += 256) {
            int r = e >> 3, q = e & 7;
            float4 va = A4[(size_t)(rowA + r)*576 + kq + q];
            float4 vb = B4[(size_t)(rowB + r)*576 + kq + q];
            int kk = 4*q;
            As[(kk+0)*68 + r] = va.x; As[(kk+1)*68 + r] = va.y;
            As[(kk+2)*68 + r] = va.z; As[(kk+3)*68 + r] = va.w;
            Bs[(kk+0)*68 + r] = vb.x; Bs[(kk+1)*68 + r] = vb.y;
            Bs[(kk+2)*68 + r] = vb.z; Bs[(kk+3)*68 + r] = vb.w;
        }
        __syncthreads();
        #pragma unroll 8
        for (int k = 0; k < 32; k++) {
            float a0 = As[k*68 + ty],      a1 = As[k*68 + ty + 16];
            float a2 = As[k*68 + ty + 32], a3 = As[k*68 + ty + 48];
            float b0 = Bs[k*68 + tx],      b1 = Bs[k*68 + tx + 16];
            float b2 = Bs[k*68 + tx + 32], b3 = Bs[k*68 + tx + 48];
            acc[0][0]=fmaf(a0,b0,acc[0][0]); acc[0][1]=fmaf(a0,b1,acc[0][1]);
            acc[0][2]=fmaf(a0,b2,acc[0][2]); acc[0][3]=fmaf(a0,b3,acc[0][3]);
            acc[1][0]=fmaf(a1,b0,acc[1][0]); acc[1][1]=fmaf(a1,b1,acc[1][1]);
            acc[1][2]=fmaf(a1,b2,acc[1][2]); acc[1][3]=fmaf(a1,b3,acc[1][3]);
            acc[2][0]=fmaf(a2,b0,acc[2][0]); acc[2][1]=fmaf(a2,b1,acc[2][1]);
            acc[2][2]=fmaf(a2,b2,acc[2][2]); acc[2][3]=fmaf(a2,b3,acc[2][3]);
            acc[3][0]=fmaf(a3,b0,acc[3][0]); acc[3][1]=fmaf(a3,b1,acc[3][1]);
            acc[3][2]=fmaf(a3,b2,acc[3][2]); acc[3][3]=fmaf(a3,b3,acc[3][3]);
        }
    }
    float* out = g_Gp + (size_t)bz * BN * BN;
    #pragma unroll
    for (int i = 0; i < 4; i++)
        #pragma unroll
        for (int j = 0; j < 4; j++)
            out[(size_t)(rowA + ty + 16*i)*BN + rowB + tx + 16*j] = acc[i][j];
}

__global__ void reduce_scale_kernel(const float* __restrict__ scale_p) {
    const size_t i = (size_t)blockIdx.x * 512 + threadIdx.x;
    const float s = scale_p[0] / (float)CC;
    float v = 0.f;
    #pragma unroll
    for (int j = 0; j < KSPLIT; j++) v += g_Gp[(size_t)j*BN*BN + i];
    g_L[i] = s * v;
}

// --------------------------- LSE + finalize ----------------------------------
__global__ void row_lse_kernel() {
    __shared__ float red[256];
    const int b = blockIdx.x, t = threadIdx.x;
    const float* row = g_L + (size_t)b * BN;
    float x0 = row[t], x1 = row[t + 256];
    red[t] = fmaxf(x0, x1);
    __syncthreads();
    for (int st = 128; st > 0; st >>= 1) {
        if (t < st) red[t] = fmaxf(red[t], red[t + st]);
        __syncthreads();
    }
    float M = red[0];
    __syncthreads();
    red[t] = expf(x0 - M) + expf(x1 - M);
    __syncthreads();
    for (int st = 128; st > 0; st >>= 1) {
        if (t < st) red[t] += red[t + st];
        __syncthreads();
    }
    if (t == 0) g_lse_row[b] = M + logf(red[0]);
}

__global__ void col_lse_kernel() {
    __shared__ float red[256];
    const int b = blockIdx.x, t = threadIdx.x;
    float x0 = g_L[(size_t)t * BN + b], x1 = g_L[(size_t)(t + 256) * BN + b];
    red[t] = fmaxf(x0, x1);
    __syncthreads();
    for (int st = 128; st > 0; st >>= 1) {
        if (t < st) red[t] = fmaxf(red[t], red[t + st]);
        __syncthreads();
    }
    float M = red[0];
    __syncthreads();
    red[t] = expf(x0 - M) + expf(x1 - M);
    __syncthreads();
    for (int st = 128; st > 0; st >>= 1) {
        if (t < st) red[t] += red[t + st];
        __syncthreads();
    }
    if (t == 0) g_lse_col[b] = M + logf(red[0]);
}

__global__ void finalize_kernel(float* __restrict__ out) {
    __shared__ float r1[512], r2[512], r3[512];
    const int t = threadIdx.x;
    float diag = g_L[(size_t)t * BN + t];
    r1[t] = g_lse_row[t] - diag;
    r2[t] = g_lse_col[t] - diag;
    r3[t] = (t < NBLK) ? g_ot_part[t] : 0.f;
    __syncthreads();
    for (int st = 256; st > 0; st >>= 1) {
        if (t < st) { r1[t] += r1[t+st]; r2[t] += r2[t+st]; r3[t] += r3[t+st]; }
        __syncthreads();
    }
    if (t == 0)
        out[0] = (r1[0] + r2[0]) * (0.5f / (float)BN) + r3[0];
}

// ------------------------------- launch --------------------------------------
extern "C" void kernel_launch(void* const* d_in, const int* in_sizes, int n_in,
                              void* d_out, int out_size) {
    (void)in_sizes; (void)n_in; (void)out_size;
    const float* img   = (const float*)d_in[0];
    const float* txt   = (const float*)d_in[1];
    const float* scale = (const float*)d_in[2];
    const float* li    = (const float*)d_in[3];
    const float* lt    = (const float*)d_in[4];
    float* out = (float*)d_out;

    const size_t sk_smem = (size_t)(12*SKP + 12*52 + 12*80 + 3*STPB) * sizeof(float);
    cudaFuncSetAttribute(sinkhorn_kernel,
                         cudaFuncAttributeMaxDynamicSharedMemorySize, (int)sk_smem);

    init_state_kernel<<<1, 1>>>();
    simK_kernel<<<BN*CC, 256>>>(li, lt);
    sinkhorn_kernel<<<NBLK, STPB, sk_smem>>>();
    dim3 gg(8, 8, KSPLIT);
    gemm_logits_kernel<<<gg, 256>>>(img, txt);
    reduce_scale_kernel<<<512, 512>>>(scale);
    row_lse_kernel<<<BN, 256>>>();
    col_lse_kernel<<<BN, 256>>>();
    finalize_kernel<<<1, 512>>>(out);
}